// round 5
// baseline (speedup 1.0000x reference)
#include <cuda_runtime.h>
#include <cstdint>

#define NN 1024
#define EPS 1e-9
#define NBLK 148
#define NTHR 512
#define GSZ (NBLK * NTHR)

// ---- scratch (device globals; no allocation allowed) ----
__device__ double g_D[(size_t)NN * NN];   // D[d][i] = dp[i, i+d], span-major
__device__ double g_S[(size_t)NN * NN];   // premasked scores, f64
__device__ float  g_c[(size_t)NN * NN];   // premasked scores, f32 (for output)
__device__ int    g_base[NN];
__device__ unsigned g_bar_arrive;
__device__ unsigned g_bar_gen;

// ---------------- base indices + barrier init ----------------
__global__ void k_base(const float* __restrict__ feat) {
    int i = blockIdx.x * blockDim.x + threadIdx.x;
    if (i == 0) { g_bar_arrive = 0u; g_bar_gen = 0u; }
    if (i < NN) {
        float best = feat[(size_t)i * NN];  // ch 0
        int bi = 0;
        #pragma unroll
        for (int ch = 1; ch < 4; ch++) {
            float v = feat[(size_t)ch * NN * NN + (size_t)i * NN];
            if (v > best) { best = v; bi = ch; }  // strict > == first occurrence
        }
        g_base[i] = bi;
    }
}

// ---------------- premask + zero output ----------------
__global__ void k_premask(const float* __restrict__ con, float* __restrict__ out) {
    int j = blockIdx.x * blockDim.x + threadIdx.x;
    int i = blockIdx.y;
    const int pr[4] = {2, 3, 5, 7};
    float c = 0.5f * (con[(size_t)i * NN + j] + con[(size_t)j * NN + i]);
    int dd = i - j; if (dd < 0) dd = -dd;
    int prod = pr[g_base[i]] * pr[g_base[j]];
    bool ok = (dd >= 4) && (prod == 14 || prod == 15 || prod == 35);
    float cv = ok ? c : 0.0f;
    g_c[(size_t)i * NN + j] = cv;
    g_S[(size_t)i * NN + j] = (double)cv;
    out[(size_t)i * NN + j] = 0.0f;
}

// ---------------- grid-wide barrier ----------------
__device__ __forceinline__ void gridbar(unsigned& lgen) {
    __syncthreads();
    if (threadIdx.x == 0) {
        __threadfence();                       // publish this block's stores
        unsigned target = lgen + 1;
        if (atomicAdd(&g_bar_arrive, 1u) == NBLK - 1) {
            atomicExch(&g_bar_arrive, 0u);     // reset BEFORE releasing gen
            __threadfence();
            atomicAdd(&g_bar_gen, 1u);
        } else {
            while (*(volatile unsigned*)&g_bar_gen < target) __nanosleep(128);
        }
        __threadfence();                       // acquire: CCTL.IVALL -> fresh L1D
    }
    __syncthreads();
    lgen++;
}

// ---------------- persistent DP over all anti-diagonals ----------------
// cell i on diagonal d: dp[i, i+d]
//   pair  = D[d-2][i+1] + S[i][i+d]
//   split = max_{t in [0,d)} D[t][i] + D[d-1-t][i+t+1]
__global__ void __launch_bounds__(NTHR, 1) k_dp() {
    const int gtid = blockIdx.x * NTHR + threadIdx.x;
    unsigned lgen = 0;

    // zero all of g_D (covers first launch; replays recompute identical values)
    for (size_t idx = gtid; idx < (size_t)NN * NN; idx += GSZ) g_D[idx] = 0.0;
    gridbar(lgen);

    for (int d = 4; d < NN; d++) {
        const int m = NN - d;
        // chunking: K iters of t per task; keep K >= 8 to bound atomics
        int K = (d * m + GSZ - 1) / GSZ;
        if (K < 8) K = 8;
        if (K > d) K = d;
        const int C = (d + K - 1) / K;
        const int tasks = m * C;

        for (int u = gtid; u < tasks; u += GSZ) {
            const int i  = u % m;      // consecutive threads -> consecutive i (coalesced)
            const int ch = u / m;
            const int t0 = ch * K;
            const int t1 = min(d, t0 + K);

            unsigned long long best = 0ULL;
            if (ch == 0) {
                double pairv = g_D[(size_t)(d - 2) * NN + (i + 1)]
                             + g_S[(size_t)i * NN + (i + d)];
                best = (unsigned long long)__double_as_longlong(pairv);
            }

            const double* a = &g_D[(size_t)t0 * NN + i];                 // D[t][i]
            const double* b = &g_D[(size_t)(d - 1 - t0) * NN + (i + t0 + 1)];
            #pragma unroll 4
            for (int t = t0; t < t1; t++) {
                double cand = *a + *b;
                unsigned long long uu = (unsigned long long)__double_as_longlong(cand);
                best = (uu > best) ? uu : best;
                a += NN;
                b -= (NN - 1);
            }

            if (C == 1) {
                g_D[(size_t)d * NN + i] = __longlong_as_double((long long)best);
            } else {
                atomicMax((unsigned long long*)&g_D[(size_t)d * NN + i], best);
            }
        }
        gridbar(lgen);
    }
}

// ---------------- traceback (single CTA) ----------------
__global__ void k_traceback(float* __restrict__ out) {
    const int tid = threadIdx.x;  // blockDim = 256
    __shared__ int2 stk[4096];
    __shared__ int sp_s;
    __shared__ int cmd, ci, cj;
    __shared__ double rv[256];
    __shared__ int ri[256];

    if (tid == 0) { stk[0] = make_int2(0, NN - 1); sp_s = 1; }
    __syncthreads();

    long long steps = 0;
    while (true) {
        if (tid == 0) {
            cmd = 0;
            while (sp_s > 0) {
                if (++steps > 2000000LL) { cmd = 0; sp_s = 0; break; }  // safety
                int2 e = stk[--sp_s];
                int i = e.x, j = e.y;
                if (j <= i) continue;
                double v = g_D[(size_t)(j - i) * NN + i];
                if (v <= EPS) continue;
                double up = g_D[(size_t)(j - i - 1) * NN + (i + 1)];  // dp[i+1,j]
                if (up >= v - EPS) { stk[sp_s++] = make_int2(i + 1, j); continue; }
                double s = g_S[(size_t)i * NN + j];
                double inner = (j - i >= 2) ? g_D[(size_t)(j - i - 2) * NN + (i + 1)] : 0.0;
                if (s > 0.0 && inner + s >= v - EPS) {
                    out[(size_t)i * NN + j] = g_c[(size_t)i * NN + j];
                    out[(size_t)j * NN + i] = g_c[(size_t)j * NN + i];
                    stk[sp_s++] = make_int2(i + 1, j - 1);
                    continue;
                }
                cmd = 1; ci = i; cj = j;
                break;
            }
        }
        __syncthreads();
        if (cmd == 0) break;

        int i = ci, j = cj;
        double bestv = -1.0;
        int bestk = NN + 1;
        for (int k = i + tid; k < j; k += blockDim.x) {  // ascending k: strict > keeps first
            double v = g_D[(size_t)(k - i) * NN + i] + g_D[(size_t)(j - k - 1) * NN + (k + 1)];
            if (v > bestv) { bestv = v; bestk = k; }
        }
        rv[tid] = bestv; ri[tid] = bestk;
        __syncthreads();
        for (int sft = 128; sft > 0; sft >>= 1) {
            if (tid < sft) {
                double vb = rv[tid + sft]; int ib = ri[tid + sft];
                if (vb > rv[tid] || (vb == rv[tid] && ib < ri[tid])) { rv[tid] = vb; ri[tid] = ib; }
            }
            __syncthreads();
        }
        if (tid == 0) {
            int k = ri[0];
            stk[sp_s++] = make_int2(i, k);         // same push order as reference
            stk[sp_s++] = make_int2(k + 1, j);
        }
        __syncthreads();
    }
}

// ---------------- launch (4 graph nodes total) ----------------
extern "C" void kernel_launch(void* const* d_in, const int* in_sizes, int n_in,
                              void* d_out, int out_size) {
    const float* con  = (const float*)d_in[0];
    const float* feat = (const float*)d_in[1];
    float* out = (float*)d_out;

    k_base<<<(NN + 255) / 256, 256>>>(feat);
    k_premask<<<dim3(NN / 256, NN), 256>>>(con, out);
    k_dp<<<NBLK, NTHR>>>();
    k_traceback<<<1, 256>>>(out);
}